// round 5
// baseline (speedup 1.0000x reference)
#include <cuda_runtime.h>
#include <float.h>

// Problem constants
#define ZB   4
#define CD   256        // embedding dim / channels
#define ZTHW 8192       // T*H*W = 8*32*32
#define NPT  32768      // number of vectors (B*T*H*W)
#define NK   1024       // codebook size

// Output layout (float32, concatenated in reference return order)
// NOTE: OFF_D is ODD -> the d-region is 4-byte-skewed; only scalar stores there.
#define OFF_ZQ   0
#define OFF_LOSS 8388608
#define OFF_INDS 8388609
#define OFF_D    8421377

// GEMM tiling: 128x128 block tile, 8x8 per-thread micro-tile, BK=8, dbl-buffer
#define BM  128
#define BN  128
#define BK  8
#define NTILES (NK / BN)   // 8
#define KTILES (CD / BK)   // 32

// Scratch (device globals; no allocations allowed)
__device__ float  g_xnorm[NPT];
__device__ float  g_enorm[NK];
__device__ int    g_inds[NPT];
__device__ double g_part[256];

// ---------------------------------------------------------------------------
// ||e_k||^2 per code row (one warp per row)
// ---------------------------------------------------------------------------
__global__ void vq_enorm(const float* __restrict__ E) {
    int warp = (blockIdx.x * blockDim.x + threadIdx.x) >> 5;
    int lane = threadIdx.x & 31;
    if (warp >= NK) return;
    const float* row = E + (size_t)warp * CD;
    float s = 0.f;
    #pragma unroll
    for (int c = lane; c < CD; c += 32) { float v = row[c]; s = fmaf(v, v, s); }
    #pragma unroll
    for (int off = 16; off; off >>= 1) s += __shfl_xor_sync(0xFFFFFFFFu, s, off);
    if (lane == 0) g_enorm[warp] = s;
}

// ---------------------------------------------------------------------------
// ||x_n||^2 per point; z is [B,C,THW] so the c-strided loop is coalesced in n.
// ---------------------------------------------------------------------------
__global__ void vq_xnorm(const float* __restrict__ z) {
    int n = blockIdx.x * blockDim.x + threadIdx.x;
    int b = n >> 13, thw = n & (ZTHW - 1);
    const float* p = z + (size_t)b * CD * ZTHW + thw;
    float s = 0.f;
    #pragma unroll 8
    for (int c = 0; c < CD; c++) {
        float v = p[(size_t)c * ZTHW];
        s = fmaf(v, v, s);
    }
    g_xnorm[n] = s;
}

// ---------------------------------------------------------------------------
// Fused GEMM + d-write + per-row argmin.
//   d[n,k] = ||x_n||^2 + ||e_k||^2 - 2 x_n.e_k   (full 32768x1024 fp32 write)
// B-tile smem columns are PERMUTED: within each 64-col group, column n sits at
// position (n&15)*4 + (n>>4). The LDS.128 fragment reads are unchanged, but a
// thread's fragment j maps to column 16*j + tx, so epilogue scalar stores are
// lane-consecutive (coalesced) -- required because OFF_D is 4-byte-skewed.
// ---------------------------------------------------------------------------
__global__ __launch_bounds__(256, 2) void vq_gemm(const float* __restrict__ z,
                                                  const float* __restrict__ E,
                                                  float* __restrict__ out) {
    __shared__ float As[2][BK][BM];
    __shared__ float Bs[2][BK][BN];
    __shared__ float Xn[BM];

    const int tid  = threadIdx.x;
    const int n0   = blockIdx.x * BM;        // 128 | 8192 -> no batch crossing
    const int b    = n0 >> 13;
    const int thw0 = n0 & (ZTHW - 1);
    const float* zb = z + (size_t)b * CD * ZTHW + thw0;

    // A-tile loader: thread -> (c = tid>>5 in 0..7, m = (tid&31)*4), float4
    const int a_c = tid >> 5;
    const int a_m = (tid & 31) << 2;
    // B-tile loader: thread -> (n = tid>>1 in 0..127, c = (tid&1)*4), float4
    const int b_n = tid >> 1;
    const int b_c = (tid & 1) << 2;
    // permuted smem position for column b_n
    const int b_pos = (b_n & 64) | ((b_n & 15) << 2) | ((b_n & 48) >> 4);

    if (tid < BM) Xn[tid] = g_xnorm[n0 + tid];

    const int tx = tid & 15, ty = tid >> 4;

    float best[8];
    int   bidr[8];
    #pragma unroll
    for (int i = 0; i < 8; i++) { best[i] = FLT_MAX; bidr[i] = 0; }

    for (int nt = 0; nt < NTILES; nt++) {
        const int k0 = nt * BN;
        float acc[8][8];
        #pragma unroll
        for (int i = 0; i < 8; i++)
            #pragma unroll
            for (int j = 0; j < 8; j++) acc[i][j] = 0.f;

        // prefetch k-tile 0 into stage 0
        float4 aReg = *(const float4*)&zb[(size_t)a_c * ZTHW + a_m];
        float4 bReg = *(const float4*)&E[(size_t)(k0 + b_n) * CD + b_c];
        *(float4*)&As[0][a_c][a_m] = aReg;
        Bs[0][b_c + 0][b_pos] = bReg.x;
        Bs[0][b_c + 1][b_pos] = bReg.y;
        Bs[0][b_c + 2][b_pos] = bReg.z;
        Bs[0][b_c + 3][b_pos] = bReg.w;
        __syncthreads();

        for (int kt = 0; kt < KTILES; kt++) {
            const int cur = kt & 1;
            if (kt + 1 < KTILES) {
                const int cc = (kt + 1) * BK;
                aReg = *(const float4*)&zb[(size_t)(cc + a_c) * ZTHW + a_m];
                bReg = *(const float4*)&E[(size_t)(k0 + b_n) * CD + cc + b_c];
            }
            #pragma unroll
            for (int k = 0; k < BK; k++) {
                float4 a0 = *(const float4*)&As[cur][k][ty * 4];
                float4 a1 = *(const float4*)&As[cur][k][64 + ty * 4];
                float4 b0 = *(const float4*)&Bs[cur][k][tx * 4];
                float4 b1 = *(const float4*)&Bs[cur][k][64 + tx * 4];
                float av[8] = {a0.x, a0.y, a0.z, a0.w, a1.x, a1.y, a1.z, a1.w};
                float bv[8] = {b0.x, b0.y, b0.z, b0.w, b1.x, b1.y, b1.z, b1.w};
                #pragma unroll
                for (int i = 0; i < 8; i++)
                    #pragma unroll
                    for (int j = 0; j < 8; j++)
                        acc[i][j] = fmaf(av[i], bv[j], acc[i][j]);
            }
            if (kt + 1 < KTILES) {
                const int nxt = cur ^ 1;
                *(float4*)&As[nxt][a_c][a_m] = aReg;
                Bs[nxt][b_c + 0][b_pos] = bReg.x;
                Bs[nxt][b_c + 1][b_pos] = bReg.y;
                Bs[nxt][b_c + 2][b_pos] = bReg.z;
                Bs[nxt][b_c + 3][b_pos] = bReg.w;
            }
            __syncthreads();
        }

        // epilogue: fragment j <-> column 16*j+tx (j<4) or 64+16*(j-4)+tx.
        // Scalar loads/stores; lanes consecutive in tx -> fully coalesced.
        float en[8];
        #pragma unroll
        for (int j = 0; j < 8; j++) {
            const int kc = (j < 4) ? (16 * j + tx) : (64 + 16 * (j - 4) + tx);
            en[j] = g_enorm[k0 + kc];
        }
        float* dout = out + OFF_D + (size_t)n0 * NK + k0;
        #pragma unroll
        for (int i = 0; i < 8; i++) {
            const int m  = (i < 4) ? (ty * 4 + i) : (64 + ty * 4 + i - 4);
            const float xn = Xn[m];
            float* dr = dout + (size_t)m * NK;
            #pragma unroll
            for (int j = 0; j < 8; j++) {
                const int kc = (j < 4) ? (16 * j + tx) : (64 + 16 * (j - 4) + tx);
                const float dv = xn + en[j] - 2.0f * acc[i][j];
                dr[kc] = dv;
                if (dv < best[i]) { best[i] = dv; bidr[i] = k0 + kc; }
            }
        }
    }

    // argmin reduce across the 16 tx lanes per row (first-index tie-break)
    #pragma unroll
    for (int i = 0; i < 8; i++) {
        float v  = best[i];
        int   id = bidr[i];
        #pragma unroll
        for (int off = 8; off >= 1; off >>= 1) {
            float v2 = __shfl_xor_sync(0xFFFFFFFFu, v, off);
            int   i2 = __shfl_xor_sync(0xFFFFFFFFu, id, off);
            if (v2 < v || (v2 == v && i2 < id)) { v = v2; id = i2; }
        }
        if (tx == 0) {
            const int m = (i < 4) ? (ty * 4 + i) : (64 + ty * 4 + i - 4);
            const int n = n0 + m;
            g_inds[n] = id;
            out[OFF_INDS + n] = (float)id;
        }
    }
}

// ---------------------------------------------------------------------------
// Gather z_q, emit z_q_ste = z + (z_q - z) (exact fp op order), accumulate
// sum((z_q - z)^2) into deterministic per-block double partials.
// ---------------------------------------------------------------------------
__global__ __launch_bounds__(256) void vq_out(const float* __restrict__ z,
                                              const float* __restrict__ E,
                                              float* __restrict__ out) {
    int n = blockIdx.x * blockDim.x + threadIdx.x;
    int b = n >> 13, thw = n & (ZTHW - 1);
    const float* zp = z + (size_t)b * CD * ZTHW + thw;
    float* op = out + OFF_ZQ + (size_t)b * CD * ZTHW + thw;
    int row = g_inds[n];
    const float4* er = (const float4*)(E + (size_t)row * CD);

    float local = 0.f;
    #pragma unroll 4
    for (int c4 = 0; c4 < CD / 4; c4++) {
        float4 e4 = er[c4];
        float ev[4] = {e4.x, e4.y, e4.z, e4.w};
        #pragma unroll
        for (int j = 0; j < 4; j++) {
            int c = c4 * 4 + j;
            float zv = zp[(size_t)c * ZTHW];
            float t  = __fsub_rn(ev[j], zv);          // z_q - z
            op[(size_t)c * ZTHW] = __fadd_rn(zv, t);  // z + (z_q - z)
            local = fmaf(t, t, local);
        }
    }
    #pragma unroll
    for (int off = 16; off; off >>= 1) local += __shfl_xor_sync(0xFFFFFFFFu, local, off);
    __shared__ float ws[8];
    int lane = threadIdx.x & 31, w = threadIdx.x >> 5;
    if (lane == 0) ws[w] = local;
    __syncthreads();
    if (threadIdx.x == 0) {
        double s = 0.0;
        #pragma unroll
        for (int i = 0; i < 8; i++) s += (double)ws[i];
        g_part[blockIdx.x] = s;
    }
}

__global__ void vq_finalize(float* __restrict__ out, int npart) {
    if (threadIdx.x == 0 && blockIdx.x == 0) {
        double s = 0.0;
        for (int i = 0; i < npart; i++) s += g_part[i];
        // codebook_loss + BETA*commit_loss = (1 + 0.25) * mean((z_q - z)^2)
        out[OFF_LOSS] = (float)(1.25 * s / 8388608.0);
    }
}

// ---------------------------------------------------------------------------
extern "C" void kernel_launch(void* const* d_in, const int* in_sizes, int n_in,
                              void* d_out, int out_size) {
    const float* z = (const float*)d_in[0];
    const float* E = (const float*)d_in[1];
    float* out = (float*)d_out;

    vq_enorm<<<128, 256>>>(E);
    vq_xnorm<<<128, 256>>>(z);
    vq_gemm<<<NPT / BM, 256>>>(z, E, out);        // 256 blocks, static smem only
    vq_out<<<NPT / 256, 256>>>(z, E, out);
    vq_finalize<<<1, 32>>>(out, NPT / 256);
}

// round 8
// speedup vs baseline: 1.1675x; 1.1675x over previous
#include <cuda_runtime.h>
#include <cuda_fp16.h>
#include <float.h>
#include <stdint.h>

// Problem constants
#define CD   256
#define ZTHW 8192
#define NPT  32768
#define NK   1024

// Output layout (float32). OFF_D is ODD -> only scalar stores in d region.
#define OFF_ZQ   0
#define OFF_LOSS 8388608
#define OFF_INDS 8388609
#define OFF_D    8421377

#define GAP_THRESH 1e-4f

// Scratch globals
__device__ __align__(16) __half g_zth[NPT * CD];   // z^T hi plane [n][c]
__device__ __align__(16) __half g_ztl[NPT * CD];   // z^T lo plane [n][c]
__device__ __align__(16) __half g_Eh[NK * CD];     // E fp16 [k][c]
__device__ float  g_xnorm[NPT];
__device__ float  g_enorm[NK];
__device__ int    g_inds[NPT];
__device__ double g_part[512];
__device__ int    g_nflag;
__device__ int    g_flag[NPT];

// ---------------------------------------------------------------------------
// PTX helpers (portable sm_80+ only: mma.sync / ldmatrix / cp.async)
// ---------------------------------------------------------------------------
__device__ __forceinline__ uint32_t smem_u32(const void* p) {
    uint32_t a;
    asm("{ .reg .u64 t; cvta.to.shared.u64 t, %1; cvt.u32.u64 %0, t; }" : "=r"(a) : "l"(p));
    return a;
}
__device__ __forceinline__ void ldsm_x4(uint32_t& r0, uint32_t& r1, uint32_t& r2,
                                        uint32_t& r3, uint32_t addr) {
    asm volatile("ldmatrix.sync.aligned.m8n8.x4.shared.b16 {%0,%1,%2,%3}, [%4];"
                 : "=r"(r0), "=r"(r1), "=r"(r2), "=r"(r3) : "r"(addr));
}
__device__ __forceinline__ void mma16816(float* c, const uint32_t* a, const uint32_t* b) {
    asm volatile(
        "mma.sync.aligned.m16n8k16.row.col.f32.f16.f16.f32 "
        "{%0,%1,%2,%3}, {%4,%5,%6,%7}, {%8,%9}, {%0,%1,%2,%3};"
        : "+f"(c[0]), "+f"(c[1]), "+f"(c[2]), "+f"(c[3])
        : "r"(a[0]), "r"(a[1]), "r"(a[2]), "r"(a[3]), "r"(b[0]), "r"(b[1]));
}
__device__ __forceinline__ void cp16(uint32_t dst, const void* src) {
    asm volatile("cp.async.cg.shared.global [%0], [%1], 16;" :: "r"(dst), "l"(src));
}
#define CP_COMMIT() asm volatile("cp.async.commit_group;" ::: "memory")
#define CP_WAIT(N)  asm volatile("cp.async.wait_group %0;" :: "n"(N) : "memory")

// GEMM smem layout (bytes)
#define APAD   264                    // 256 halves + 8 pad (row stride 528B)
#define EPAD   72                     // 64 halves + 8 pad  (row stride 144B)
#define A_PLANE (128 * APAD * 2)      // 67584
#define SM_A    0
#define SM_E    (2 * A_PLANE)         // 135168; 2 bufs x 128 x 72 x 2 = 36864
#define E_BUF   (128 * EPAD * 2)      // 18432
#define SM_XN   (SM_E + 2 * E_BUF)    // 172032 (128 floats)
#define SM_TOT  (SM_XN + 512)         // 172544

// ---------------------------------------------------------------------------
// Transpose+split z: [B,C,THW] fp32 -> [N][C] fp16 hi/lo planes. 64x64 tiles.
// ---------------------------------------------------------------------------
__global__ __launch_bounds__(256) void conv_z(const float* __restrict__ z) {
    __shared__ float tile[64][65];
    const int bx = blockIdx.x;
    const int ct = bx & 3, tt = (bx >> 2) & 127, b = bx >> 9;
    const int tid = threadIdx.x;

    const int c_l = tid >> 4, t4 = (tid & 15) << 2;
    #pragma unroll
    for (int cc = 0; cc < 4; cc++) {
        const int c_idx = cc * 16 + c_l;
        const float4 v = *(const float4*)&z[((size_t)(b * CD + ct * 64 + c_idx)) * ZTHW
                                            + tt * 64 + t4];
        tile[c_idx][t4 + 0] = v.x; tile[c_idx][t4 + 1] = v.y;
        tile[c_idx][t4 + 2] = v.z; tile[c_idx][t4 + 3] = v.w;
    }
    __syncthreads();

    const int t_l = tid >> 2, cs = (tid & 3) << 4;
    const size_t n = (size_t)b * ZTHW + tt * 64 + t_l;
    __half h[16], l[16];
    #pragma unroll
    for (int j = 0; j < 16; j++) {
        const float x = tile[cs + j][t_l];
        const __half hv = __float2half_rn(x);
        h[j] = hv;
        l[j] = __float2half_rn(x - __half2float(hv));
    }
    __half* dh = g_zth + n * CD + ct * 64 + cs;
    __half* dl = g_ztl + n * CD + ct * 64 + cs;
    *(uint4*)(dh + 0) = ((uint4*)h)[0];  *(uint4*)(dh + 8) = ((uint4*)h)[1];
    *(uint4*)(dl + 0) = ((uint4*)l)[0];  *(uint4*)(dl + 8) = ((uint4*)l)[1];
}

__global__ void conv_E(const float* __restrict__ E) {
    const int i4 = blockIdx.x * blockDim.x + threadIdx.x;
    if (i4 == 0) g_nflag = 0;
    const float4 v = ((const float4*)E)[i4];
    __half h[4] = {__float2half_rn(v.x), __float2half_rn(v.y),
                   __float2half_rn(v.z), __float2half_rn(v.w)};
    *(uint2*)&g_Eh[(size_t)i4 * 4] = *(uint2*)h;
}

// ---------------------------------------------------------------------------
// Norms
// ---------------------------------------------------------------------------
__global__ void vq_enorm(const float* __restrict__ E) {
    int warp = (blockIdx.x * blockDim.x + threadIdx.x) >> 5;
    int lane = threadIdx.x & 31;
    if (warp >= NK) return;
    const float* row = E + (size_t)warp * CD;
    float s = 0.f;
    #pragma unroll
    for (int c = lane; c < CD; c += 32) { float v = row[c]; s = fmaf(v, v, s); }
    #pragma unroll
    for (int off = 16; off; off >>= 1) s += __shfl_xor_sync(0xFFFFFFFFu, s, off);
    if (lane == 0) g_enorm[warp] = s;
}

__global__ void vq_xnorm(const float* __restrict__ z) {
    int t = blockIdx.x * blockDim.x + threadIdx.x;
    int p = t >> 2, q = t & 3;
    int b = p >> 13, thw = p & (ZTHW - 1);
    const float* zp = z + (size_t)b * CD * ZTHW + thw;
    float s = 0.f;
    #pragma unroll 8
    for (int c = q * 64; c < q * 64 + 64; c++) {
        float v = zp[(size_t)c * ZTHW];
        s = fmaf(v, v, s);
    }
    s += __shfl_xor_sync(0xFFFFFFFFu, s, 1);
    s += __shfl_xor_sync(0xFFFFFFFFu, s, 2);
    if (q == 0) g_xnorm[p] = s;
}

// ---------------------------------------------------------------------------
// mma.sync GEMM: CTA = 128 pts x 128 codes/ct-tile, 8 ct tiles, K=256.
// z hi/lo resident in smem; E streamed 64-ch stages (cp.async dbl-buffer).
// Warp tile 32x64 (2 m-tiles x 8 n-tiles, m16n8k16). acc += z_hi*E + z_lo*E.
// Epilogue tracks top-2 per point; small-gap points are flagged for exact
// fp32 refinement (fp16 noise ~4e-6 rms vs fp32 d-ulp 3e-5).
// ---------------------------------------------------------------------------
extern __shared__ char dsm[];

__global__ void __launch_bounds__(256, 1) vq_gemm_mma(float* __restrict__ out) {
    const uint32_t smu = smem_u32(dsm);
    const int tid = threadIdx.x;
    const int lane = tid & 31, wid = tid >> 5;
    const int wy = wid >> 1, wx = wid & 1;
    const int n0 = blockIdx.x * 128;

    float* xn_sm = (float*)(dsm + SM_XN);
    if (tid < 128) xn_sm[tid] = g_xnorm[n0 + tid];

    // Resident A (2 planes x 128 rows x 512B) + E stage 0; one cp.async group.
    {
        #pragma unroll
        for (int it = 0; it < 32; it++) {
            const int id = it * 256 + tid;           // 0..8191 16B chunks
            const int plane = id >> 12;
            const int row = (id >> 5) & 127;
            const int ch  = id & 31;
            const __half* src = (plane ? g_ztl : g_zth) + (size_t)(n0 + row) * CD + ch * 8;
            cp16(smu + SM_A + plane * A_PLANE + row * (APAD * 2) + ch * 16, src);
        }
        #pragma unroll
        for (int it = 0; it < 4; it++) {
            const int id = it * 256 + tid;           // 0..1023
            const int code = id >> 3, ch = id & 7;   // stage0: ct=0, kq=0
            cp16(smu + SM_E + code * (EPAD * 2) + ch * 16,
                 g_Eh + (size_t)code * CD + ch * 8);
        }
        CP_COMMIT();
    }

    const uint32_t aBase = smu + SM_A + (wy * 32 + (lane & 15)) * (APAD * 2)
                           + ((lane & 16) ? 16 : 0);
    const uint32_t bBase = smu + SM_E
                           + (wx * 64 + (lane & 7) + ((lane & 16) ? 8 : 0)) * (EPAD * 2)
                           + ((lane & 8) ? 16 : 0);

    float acc[2][8][4];
    float best[4], sec[4];
    int   bidr[4];
    #pragma unroll
    for (int i = 0; i < 4; i++) { best[i] = FLT_MAX; sec[i] = FLT_MAX; bidr[i] = 0; }

    for (int s = 0; s < 32; s++) {                   // stage = ct*4 + kq
        const int ct = s >> 2, kq = s & 3, buf = s & 1;
        if ((s & 3) == 0) {
            #pragma unroll
            for (int mt = 0; mt < 2; mt++)
                #pragma unroll
                for (int nt = 0; nt < 8; nt++)
                    #pragma unroll
                    for (int c = 0; c < 4; c++) acc[mt][nt][c] = 0.f;
        }
        if (s < 31) {
            const int ns = s + 1;
            const int nct = ns >> 2, nkq = ns & 3, nbuf = ns & 1;
            #pragma unroll
            for (int it = 0; it < 4; it++) {
                const int id = it * 256 + tid;
                const int code = id >> 3, ch = id & 7;
                cp16(smu + SM_E + nbuf * E_BUF + code * (EPAD * 2) + ch * 16,
                     g_Eh + (size_t)(nct * 128 + code) * CD + nkq * 64 + ch * 8);
            }
            CP_COMMIT();
            CP_WAIT(1);
        } else {
            CP_WAIT(0);
        }
        __syncthreads();

        #pragma unroll
        for (int step = 0; step < 4; step++) {
            const int kh_abs = kq * 64 + step * 16;
            const int kh_loc = step * 16;
            uint32_t bf[8][2];
            #pragma unroll
            for (int p4 = 0; p4 < 4; p4++) {
                uint32_t r0, r1, r2, r3;
                ldsm_x4(r0, r1, r2, r3,
                        bBase + buf * E_BUF + p4 * 16 * (EPAD * 2) + kh_loc * 2);
                bf[p4 * 2][0] = r0; bf[p4 * 2][1] = r1;
                bf[p4 * 2 + 1][0] = r2; bf[p4 * 2 + 1][1] = r3;
            }
            #pragma unroll
            for (int plane = 0; plane < 2; plane++) {
                uint32_t af[2][4];
                #pragma unroll
                for (int mt = 0; mt < 2; mt++)
                    ldsm_x4(af[mt][0], af[mt][1], af[mt][2], af[mt][3],
                            aBase + plane * A_PLANE + mt * 16 * (APAD * 2) + kh_abs * 2);
                #pragma unroll
                for (int mt = 0; mt < 2; mt++)
                    #pragma unroll
                    for (int nt = 0; nt < 8; nt++)
                        mma16816(acc[mt][nt], af[mt], bf[nt]);
            }
        }

        if ((s & 3) == 3) {
            const int k0 = ct * 128;
            #pragma unroll
            for (int mt = 0; mt < 2; mt++) {
                #pragma unroll
                for (int rsel = 0; rsel < 2; rsel++) {
                    const int bi_ = mt * 2 + rsel;
                    const int row = wy * 32 + mt * 16 + rsel * 8 + (lane >> 2);
                    const float xnv = xn_sm[row];
                    float* dr = out + OFF_D + (size_t)(n0 + row) * NK + k0;
                    #pragma unroll
                    for (int nt = 0; nt < 8; nt++) {
                        const int col0 = wx * 64 + nt * 8 + 2 * (lane & 3);
                        const float d0 = xnv + g_enorm[k0 + col0]
                                       - 2.0f * acc[mt][nt][rsel * 2];
                        const float d1 = xnv + g_enorm[k0 + col0 + 1]
                                       - 2.0f * acc[mt][nt][rsel * 2 + 1];
                        dr[col0] = d0;
                        dr[col0 + 1] = d1;
                        if (d0 < best[bi_]) { sec[bi_] = best[bi_]; best[bi_] = d0; bidr[bi_] = k0 + col0; }
                        else if (d0 < sec[bi_]) sec[bi_] = d0;
                        if (d1 < best[bi_]) { sec[bi_] = best[bi_]; best[bi_] = d1; bidr[bi_] = k0 + col0 + 1; }
                        else if (d1 < sec[bi_]) sec[bi_] = d1;
                    }
                }
            }
        }
        __syncthreads();
    }

    // quad reduce (lanes differing in bits 0-1 share rows): top-2 merge
    #pragma unroll
    for (int i = 0; i < 4; i++) {
        #pragma unroll
        for (int off = 1; off <= 2; off <<= 1) {
            const float v1o = __shfl_xor_sync(0xFFFFFFFFu, best[i], off);
            const int   i1o = __shfl_xor_sync(0xFFFFFFFFu, bidr[i], off);
            const float v2o = __shfl_xor_sync(0xFFFFFFFFu, sec[i], off);
            if (v1o < best[i] || (v1o == best[i] && i1o < bidr[i])) {
                sec[i]  = fminf(best[i], v2o);
                best[i] = v1o; bidr[i] = i1o;
            } else {
                sec[i] = fminf(sec[i], v1o);
            }
        }
    }
    // cross warp-pair reduce via smem scratch (E buffers dead after last sync)
    float* sv1 = (float*)(dsm + SM_E);
    int*   si1 = (int*)(dsm + SM_E + 512);
    float* sv2 = (float*)(dsm + SM_E + 1024);
    if (wx == 1 && (lane & 3) == 0) {
        #pragma unroll
        for (int i = 0; i < 4; i++) {
            const int row = wy * 32 + i * 8 + (lane >> 2);
            sv1[row] = best[i]; si1[row] = bidr[i]; sv2[row] = sec[i];
        }
    }
    __syncthreads();
    if (wx == 0 && (lane & 3) == 0) {
        #pragma unroll
        for (int i = 0; i < 4; i++) {
            const int row = wy * 32 + i * 8 + (lane >> 2);
            float v1 = best[i], v2 = sec[i]; int i1 = bidr[i];
            const float o1 = sv1[row], o2 = sv2[row]; const int oi = si1[row];
            if (o1 < v1 || (o1 == v1 && oi < i1)) {
                v2 = fminf(v1, o2); v1 = o1; i1 = oi;
            } else {
                v2 = fminf(v2, o1);
            }
            const int n = n0 + row;
            g_inds[n] = i1;
            out[OFF_INDS + n] = (float)i1;
            if (v2 - v1 < GAP_THRESH) {
                int slot = atomicAdd(&g_nflag, 1);
                g_flag[slot] = n;
            }
        }
    }
}

// ---------------------------------------------------------------------------
// Exact fp32 refinement for flagged (ambiguous-gap) points. Block per point,
// 8 warps x 128 codes; first-index-wins tie-breaking throughout.
// ---------------------------------------------------------------------------
__global__ __launch_bounds__(256) void vq_refine(const float* __restrict__ z,
                                                 const float* __restrict__ E,
                                                 float* __restrict__ out) {
    __shared__ float zs[256];
    __shared__ float wv[8];
    __shared__ int   wi[8];
    const int nf = g_nflag;
    const int tid = threadIdx.x, w = tid >> 5, lane = tid & 31;

    for (int f = blockIdx.x; f < nf; f += gridDim.x) {
        const int p = g_flag[f];
        const int b = p >> 13, thw = p & (ZTHW - 1);
        const float* zp = z + (size_t)b * CD * ZTHW + thw;
        zs[tid] = zp[(size_t)tid * ZTHW];
        __syncthreads();

        const float xn = g_xnorm[p];
        float bv = FLT_MAX; int bi = 0;
        for (int j = 0; j < 128; j++) {
            const int k = w * 128 + j;
            const float* er = E + (size_t)k * CD;
            float dot = 0.f;
            #pragma unroll
            for (int i = 0; i < 8; i++)
                dot = fmaf(er[lane + 32 * i], zs[lane + 32 * i], dot);
            #pragma unroll
            for (int off = 16; off; off >>= 1)
                dot += __shfl_xor_sync(0xFFFFFFFFu, dot, off);
            const float d = xn + g_enorm[k] - 2.0f * dot;
            if (d < bv) { bv = d; bi = k; }       // j ascending -> first wins
        }
        if (lane == 0) { wv[w] = bv; wi[w] = bi; }
        __syncthreads();
        if (tid == 0) {
            float v = wv[0]; int id = wi[0];
            #pragma unroll
            for (int w2 = 1; w2 < 8; w2++)
                if (wv[w2] < v) { v = wv[w2]; id = wi[w2]; }  // ascending w -> first wins
            g_inds[p] = id;
            out[OFF_INDS + p] = (float)id;
        }
        __syncthreads();
    }
}

// ---------------------------------------------------------------------------
// Gather z_q, z_q_ste = z + (z_q - z), deterministic loss partials.
// ---------------------------------------------------------------------------
__global__ __launch_bounds__(256) void vq_out(const float* __restrict__ z,
                                              const float* __restrict__ E,
                                              float* __restrict__ out) {
    int t = blockIdx.x * blockDim.x + threadIdx.x;
    int p = t >> 2, q = t & 3;
    int b = p >> 13, thw = p & (ZTHW - 1);
    const float* zp = z + (size_t)b * CD * ZTHW + thw;
    float* op = out + OFF_ZQ + (size_t)b * CD * ZTHW + thw;
    int row = g_inds[p];
    const float4* er = (const float4*)(E + (size_t)row * CD + q * 64);

    float local = 0.f;
    #pragma unroll 4
    for (int c4 = 0; c4 < 16; c4++) {
        float4 e4 = er[c4];
        float ev[4] = {e4.x, e4.y, e4.z, e4.w};
        #pragma unroll
        for (int j = 0; j < 4; j++) {
            int c = q * 64 + c4 * 4 + j;
            float zv = zp[(size_t)c * ZTHW];
            float tt = __fsub_rn(ev[j], zv);
            op[(size_t)c * ZTHW] = __fadd_rn(zv, tt);
            local = fmaf(tt, tt, local);
        }
    }
    #pragma unroll
    for (int off = 16; off; off >>= 1) local += __shfl_xor_sync(0xFFFFFFFFu, local, off);
    __shared__ float ws[8];
    int lane = threadIdx.x & 31, w = threadIdx.x >> 5;
    if (lane == 0) ws[w] = local;
    __syncthreads();
    if (threadIdx.x == 0) {
        double s = 0.0;
        #pragma unroll
        for (int i = 0; i < 8; i++) s += (double)ws[i];
        g_part[blockIdx.x] = s;
    }
}

__global__ void vq_finalize(float* __restrict__ out, int npart) {
    if (threadIdx.x == 0 && blockIdx.x == 0) {
        double s = 0.0;
        for (int i = 0; i < npart; i++) s += g_part[i];
        out[OFF_LOSS] = (float)(1.25 * s / 8388608.0);
    }
}

// ---------------------------------------------------------------------------
extern "C" void kernel_launch(void* const* d_in, const int* in_sizes, int n_in,
                              void* d_out, int out_size) {
    const float* z = (const float*)d_in[0];
    const float* E = (const float*)d_in[1];
    float* out = (float*)d_out;

    conv_z<<<2048, 256>>>(z);
    conv_E<<<(NK * CD) / 1024, 256>>>(E);   // also zeroes g_nflag
    vq_enorm<<<128, 256>>>(E);
    vq_xnorm<<<512, 256>>>(z);

    cudaFuncSetAttribute(vq_gemm_mma, cudaFuncAttributeMaxDynamicSharedMemorySize, SM_TOT);
    vq_gemm_mma<<<NPT / 128, 256, SM_TOT>>>(out);

    vq_refine<<<592, 256>>>(z, E, out);
    vq_out<<<512, 256>>>(z, E, out);
    vq_finalize<<<1, 32>>>(out, 512);
}

// round 9
// speedup vs baseline: 1.4277x; 1.2229x over previous
#include <cuda_runtime.h>
#include <cuda_fp16.h>
#include <float.h>
#include <stdint.h>

// Problem constants
#define CD   256
#define ZTHW 8192
#define NPT  32768
#define NK   1024

// Output layout (float32). OFF_D is ODD -> only scalar stores in d region.
#define OFF_ZQ   0
#define OFF_LOSS 8388608
#define OFF_INDS 8388609
#define OFF_D    8421377

#define GAP_THRESH 1e-4f

// Scratch globals
__device__ __align__(16) __half g_zth[NPT * CD];   // z^T fp16 [n][c]
__device__ __align__(16) __half g_Eh[NK * CD];     // E fp16 [k][c]
__device__ float  g_xnorm[NPT];
__device__ float  g_enorm[NK];
__device__ int    g_inds[NPT];
__device__ double g_part[512];
__device__ int    g_nflag;
__device__ int    g_flag[NPT];

// ---------------------------------------------------------------------------
// PTX helpers (portable sm_80+: mma.sync / ldmatrix / cp.async)
// ---------------------------------------------------------------------------
__device__ __forceinline__ uint32_t smem_u32(const void* p) {
    uint32_t a;
    asm("{ .reg .u64 t; cvta.to.shared.u64 t, %1; cvt.u32.u64 %0, t; }" : "=r"(a) : "l"(p));
    return a;
}
__device__ __forceinline__ void ldsm_x4(uint32_t& r0, uint32_t& r1, uint32_t& r2,
                                        uint32_t& r3, uint32_t addr) {
    asm volatile("ldmatrix.sync.aligned.m8n8.x4.shared.b16 {%0,%1,%2,%3}, [%4];"
                 : "=r"(r0), "=r"(r1), "=r"(r2), "=r"(r3) : "r"(addr));
}
__device__ __forceinline__ void mma16816(float* c, const uint32_t* a, const uint32_t* b) {
    asm volatile(
        "mma.sync.aligned.m16n8k16.row.col.f32.f16.f16.f32 "
        "{%0,%1,%2,%3}, {%4,%5,%6,%7}, {%8,%9}, {%0,%1,%2,%3};"
        : "+f"(c[0]), "+f"(c[1]), "+f"(c[2]), "+f"(c[3])
        : "r"(a[0]), "r"(a[1]), "r"(a[2]), "r"(a[3]), "r"(b[0]), "r"(b[1]));
}
__device__ __forceinline__ void cp16(uint32_t dst, const void* src) {
    asm volatile("cp.async.cg.shared.global [%0], [%1], 16;" :: "r"(dst), "l"(src));
}
#define CP_COMMIT() asm volatile("cp.async.commit_group;" ::: "memory")
#define CP_WAIT(N)  asm volatile("cp.async.wait_group %0;" :: "n"(N) : "memory")

// GEMM smem layout (bytes) -- single A plane so 2 CTAs/SM fit (2x105KB < 228KB)
#define APAD   264                    // 256 halves + 8 pad (row stride 528B)
#define EPAD   72                     // 64 halves + 8 pad  (row stride 144B)
#define A_PLANE (128 * APAD * 2)      // 67584
#define SM_A    0
#define SM_E    A_PLANE               // 67584; 2 bufs x 128 x 144 = 36864
#define E_BUF   (128 * EPAD * 2)      // 18432
#define SM_XN   (SM_E + 2 * E_BUF)    // 104448 (128 floats)
#define SM_TOT  (SM_XN + 512)         // 104960

// ---------------------------------------------------------------------------
// Transpose z: [B,C,THW] fp32 -> [N][C] fp16. 64x64 tiles.
// ---------------------------------------------------------------------------
__global__ __launch_bounds__(256) void conv_z(const float* __restrict__ z) {
    __shared__ float tile[64][65];
    const int bx = blockIdx.x;
    const int ct = bx & 3, tt = (bx >> 2) & 127, b = bx >> 9;
    const int tid = threadIdx.x;

    const int c_l = tid >> 4, t4 = (tid & 15) << 2;
    #pragma unroll
    for (int cc = 0; cc < 4; cc++) {
        const int c_idx = cc * 16 + c_l;
        const float4 v = *(const float4*)&z[((size_t)(b * CD + ct * 64 + c_idx)) * ZTHW
                                            + tt * 64 + t4];
        tile[c_idx][t4 + 0] = v.x; tile[c_idx][t4 + 1] = v.y;
        tile[c_idx][t4 + 2] = v.z; tile[c_idx][t4 + 3] = v.w;
    }
    __syncthreads();

    const int t_l = tid >> 2, cs = (tid & 3) << 4;
    const size_t n = (size_t)b * ZTHW + tt * 64 + t_l;
    __half h[16];
    #pragma unroll
    for (int j = 0; j < 16; j++) h[j] = __float2half_rn(tile[cs + j][t_l]);
    __half* dh = g_zth + n * CD + ct * 64 + cs;
    *(uint4*)(dh + 0) = ((uint4*)h)[0];  *(uint4*)(dh + 8) = ((uint4*)h)[1];
}

__global__ void conv_E(const float* __restrict__ E) {
    const int i4 = blockIdx.x * blockDim.x + threadIdx.x;
    if (i4 == 0) g_nflag = 0;
    const float4 v = ((const float4*)E)[i4];
    __half h[4] = {__float2half_rn(v.x), __float2half_rn(v.y),
                   __float2half_rn(v.z), __float2half_rn(v.w)};
    *(uint2*)&g_Eh[(size_t)i4 * 4] = *(uint2*)h;
}

// ---------------------------------------------------------------------------
// Norms
// ---------------------------------------------------------------------------
__global__ void vq_enorm(const float* __restrict__ E) {
    int warp = (blockIdx.x * blockDim.x + threadIdx.x) >> 5;
    int lane = threadIdx.x & 31;
    if (warp >= NK) return;
    const float* row = E + (size_t)warp * CD;
    float s = 0.f;
    #pragma unroll
    for (int c = lane; c < CD; c += 32) { float v = row[c]; s = fmaf(v, v, s); }
    #pragma unroll
    for (int off = 16; off; off >>= 1) s += __shfl_xor_sync(0xFFFFFFFFu, s, off);
    if (lane == 0) g_enorm[warp] = s;
}

__global__ void vq_xnorm(const float* __restrict__ z) {
    int t = blockIdx.x * blockDim.x + threadIdx.x;
    int p = t >> 3, q = t & 7;                 // 8 threads/point, 32 ch each
    int b = p >> 13, thw = p & (ZTHW - 1);
    const float* zp = z + (size_t)b * CD * ZTHW + thw;
    float s = 0.f;
    #pragma unroll 8
    for (int c = q * 32; c < q * 32 + 32; c++) {
        float v = zp[(size_t)c * ZTHW];
        s = fmaf(v, v, s);
    }
    s += __shfl_xor_sync(0xFFFFFFFFu, s, 1);
    s += __shfl_xor_sync(0xFFFFFFFFu, s, 2);
    s += __shfl_xor_sync(0xFFFFFFFFu, s, 4);
    if (q == 0) g_xnorm[p] = s;
}

// ---------------------------------------------------------------------------
// mma.sync GEMM: CTA = 128 pts x 128 codes/ct-tile, 8 ct tiles, K=256.
// Single fp16 z plane resident; E streamed 64-ch stages (cp.async dbl-buffer).
// 2 CTAs/SM. Top-2 tracked per point; small gaps flagged for fp32 refine.
// ---------------------------------------------------------------------------
extern __shared__ char dsm[];

__global__ void __launch_bounds__(256, 2) vq_gemm_mma(float* __restrict__ out) {
    const uint32_t smu = smem_u32(dsm);
    const int tid = threadIdx.x;
    const int lane = tid & 31, wid = tid >> 5;
    const int wy = wid >> 1, wx = wid & 1;
    const int n0 = blockIdx.x * 128;

    float* xn_sm = (float*)(dsm + SM_XN);
    if (tid < 128) xn_sm[tid] = g_xnorm[n0 + tid];

    // Resident A (128 rows x 512B) + E stage 0; one cp.async group.
    {
        #pragma unroll
        for (int it = 0; it < 16; it++) {
            const int id = it * 256 + tid;           // 0..4095 16B chunks
            const int row = id >> 5;
            const int ch  = id & 31;
            cp16(smu + SM_A + row * (APAD * 2) + ch * 16,
                 g_zth + (size_t)(n0 + row) * CD + ch * 8);
        }
        #pragma unroll
        for (int it = 0; it < 4; it++) {
            const int id = it * 256 + tid;           // 0..1023
            const int code = id >> 3, ch = id & 7;   // stage0: ct=0, kq=0
            cp16(smu + SM_E + code * (EPAD * 2) + ch * 16,
                 g_Eh + (size_t)code * CD + ch * 8);
        }
        CP_COMMIT();
    }

    const uint32_t aBase = smu + SM_A + (wy * 32 + (lane & 15)) * (APAD * 2)
                           + ((lane & 16) ? 16 : 0);
    const uint32_t bBase = smu + SM_E
                           + (wx * 64 + (lane & 7) + ((lane & 16) ? 8 : 0)) * (EPAD * 2)
                           + ((lane & 8) ? 16 : 0);

    float acc[2][8][4];
    float best[4], sec[4];
    int   bidr[4];
    #pragma unroll
    for (int i = 0; i < 4; i++) { best[i] = FLT_MAX; sec[i] = FLT_MAX; bidr[i] = 0; }

    for (int s = 0; s < 32; s++) {                   // stage = ct*4 + kq
        const int ct = s >> 2, kq = s & 3, buf = s & 1;
        if ((s & 3) == 0) {
            #pragma unroll
            for (int mt = 0; mt < 2; mt++)
                #pragma unroll
                for (int nt = 0; nt < 8; nt++)
                    #pragma unroll
                    for (int c = 0; c < 4; c++) acc[mt][nt][c] = 0.f;
        }
        if (s < 31) {
            const int ns = s + 1;
            const int nct = ns >> 2, nkq = ns & 3, nbuf = ns & 1;
            #pragma unroll
            for (int it = 0; it < 4; it++) {
                const int id = it * 256 + tid;
                const int code = id >> 3, ch = id & 7;
                cp16(smu + SM_E + nbuf * E_BUF + code * (EPAD * 2) + ch * 16,
                     g_Eh + (size_t)(nct * 128 + code) * CD + nkq * 64 + ch * 8);
            }
            CP_COMMIT();
            CP_WAIT(1);
        } else {
            CP_WAIT(0);
        }
        __syncthreads();

        #pragma unroll
        for (int step = 0; step < 4; step++) {
            const int kh_abs = kq * 64 + step * 16;
            const int kh_loc = step * 16;
            uint32_t bf[8][2];
            #pragma unroll
            for (int p4 = 0; p4 < 4; p4++) {
                uint32_t r0, r1, r2, r3;
                ldsm_x4(r0, r1, r2, r3,
                        bBase + buf * E_BUF + p4 * 16 * (EPAD * 2) + kh_loc * 2);
                bf[p4 * 2][0] = r0; bf[p4 * 2][1] = r1;
                bf[p4 * 2 + 1][0] = r2; bf[p4 * 2 + 1][1] = r3;
            }
            uint32_t af[2][4];
            #pragma unroll
            for (int mt = 0; mt < 2; mt++)
                ldsm_x4(af[mt][0], af[mt][1], af[mt][2], af[mt][3],
                        aBase + mt * 16 * (APAD * 2) + kh_abs * 2);
            #pragma unroll
            for (int mt = 0; mt < 2; mt++)
                #pragma unroll
                for (int nt = 0; nt < 8; nt++)
                    mma16816(acc[mt][nt], af[mt], bf[nt]);
        }

        if ((s & 3) == 3) {
            const int k0 = ct * 128;
            #pragma unroll
            for (int mt = 0; mt < 2; mt++) {
                #pragma unroll
                for (int rsel = 0; rsel < 2; rsel++) {
                    const int bi_ = mt * 2 + rsel;
                    const int row = wy * 32 + mt * 16 + rsel * 8 + (lane >> 2);
                    const float xnv = xn_sm[row];
                    float* dr = out + OFF_D + (size_t)(n0 + row) * NK + k0;
                    #pragma unroll
                    for (int nt = 0; nt < 8; nt++) {
                        const int col0 = wx * 64 + nt * 8 + 2 * (lane & 3);
                        const float d0 = xnv + g_enorm[k0 + col0]
                                       - 2.0f * acc[mt][nt][rsel * 2];
                        const float d1 = xnv + g_enorm[k0 + col0 + 1]
                                       - 2.0f * acc[mt][nt][rsel * 2 + 1];
                        dr[col0] = d0;
                        dr[col0 + 1] = d1;
                        if (d0 < best[bi_]) { sec[bi_] = best[bi_]; best[bi_] = d0; bidr[bi_] = k0 + col0; }
                        else if (d0 < sec[bi_]) sec[bi_] = d0;
                        if (d1 < best[bi_]) { sec[bi_] = best[bi_]; best[bi_] = d1; bidr[bi_] = k0 + col0 + 1; }
                        else if (d1 < sec[bi_]) sec[bi_] = d1;
                    }
                }
            }
        }
        __syncthreads();
    }

    // quad reduce (lanes differing in bits 0-1 share rows): top-2 merge
    #pragma unroll
    for (int i = 0; i < 4; i++) {
        #pragma unroll
        for (int off = 1; off <= 2; off <<= 1) {
            const float v1o = __shfl_xor_sync(0xFFFFFFFFu, best[i], off);
            const int   i1o = __shfl_xor_sync(0xFFFFFFFFu, bidr[i], off);
            const float v2o = __shfl_xor_sync(0xFFFFFFFFu, sec[i], off);
            if (v1o < best[i] || (v1o == best[i] && i1o < bidr[i])) {
                sec[i]  = fminf(best[i], v2o);
                best[i] = v1o; bidr[i] = i1o;
            } else {
                sec[i] = fminf(sec[i], v1o);
            }
        }
    }
    // cross warp-pair reduce via smem scratch (E buffers dead after last sync)
    float* sv1 = (float*)(dsm + SM_E);
    int*   si1 = (int*)(dsm + SM_E + 512);
    float* sv2 = (float*)(dsm + SM_E + 1024);
    if (wx == 1 && (lane & 3) == 0) {
        #pragma unroll
        for (int i = 0; i < 4; i++) {
            const int row = wy * 32 + i * 8 + (lane >> 2);
            sv1[row] = best[i]; si1[row] = bidr[i]; sv2[row] = sec[i];
        }
    }
    __syncthreads();
    if (wx == 0 && (lane & 3) == 0) {
        #pragma unroll
        for (int i = 0; i < 4; i++) {
            const int row = wy * 32 + i * 8 + (lane >> 2);
            float v1 = best[i], v2 = sec[i]; int i1 = bidr[i];
            const float o1 = sv1[row], o2 = sv2[row]; const int oi = si1[row];
            if (o1 < v1 || (o1 == v1 && oi < i1)) {
                v2 = fminf(v1, o2); v1 = o1; i1 = oi;
            } else {
                v2 = fminf(v2, o1);
            }
            const int n = n0 + row;
            g_inds[n] = i1;
            out[OFF_INDS + n] = (float)i1;
            if (v2 - v1 < GAP_THRESH) {
                int slot = atomicAdd(&g_nflag, 1);
                g_flag[slot] = n;
            }
        }
    }
}

// ---------------------------------------------------------------------------
// Exact fp32 refinement for flagged (ambiguous-gap) points. Block per point,
// 8 warps x 128 codes; first-index-wins tie-breaking throughout.
// ---------------------------------------------------------------------------
__global__ __launch_bounds__(256) void vq_refine(const float* __restrict__ z,
                                                 const float* __restrict__ E,
                                                 float* __restrict__ out) {
    __shared__ float zs[256];
    __shared__ float wv[8];
    __shared__ int   wi[8];
    const int nf = g_nflag;
    const int tid = threadIdx.x, w = tid >> 5, lane = tid & 31;

    for (int f = blockIdx.x; f < nf; f += gridDim.x) {
        const int p = g_flag[f];
        const int b = p >> 13, thw = p & (ZTHW - 1);
        const float* zp = z + (size_t)b * CD * ZTHW + thw;
        zs[tid] = zp[(size_t)tid * ZTHW];
        __syncthreads();

        const float xn = g_xnorm[p];
        float bv = FLT_MAX; int bi = 0;
        for (int j = 0; j < 128; j++) {
            const int k = w * 128 + j;
            const float* er = E + (size_t)k * CD;
            float dot = 0.f;
            #pragma unroll
            for (int i = 0; i < 8; i++)
                dot = fmaf(er[lane + 32 * i], zs[lane + 32 * i], dot);
            #pragma unroll
            for (int off = 16; off; off >>= 1)
                dot += __shfl_xor_sync(0xFFFFFFFFu, dot, off);
            const float d = xn + g_enorm[k] - 2.0f * dot;
            if (d < bv) { bv = d; bi = k; }       // j ascending -> first wins
        }
        if (lane == 0) { wv[w] = bv; wi[w] = bi; }
        __syncthreads();
        if (tid == 0) {
            float v = wv[0]; int id = wi[0];
            #pragma unroll
            for (int w2 = 1; w2 < 8; w2++)
                if (wv[w2] < v) { v = wv[w2]; id = wi[w2]; }  // ascending w -> first wins
            g_inds[p] = id;
            out[OFF_INDS + p] = (float)id;
        }
        __syncthreads();
    }
}

// ---------------------------------------------------------------------------
// Gather z_q, z_q_ste = z + (z_q - z), deterministic loss partials.
// ---------------------------------------------------------------------------
__global__ __launch_bounds__(256) void vq_out(const float* __restrict__ z,
                                              const float* __restrict__ E,
                                              float* __restrict__ out) {
    int t = blockIdx.x * blockDim.x + threadIdx.x;
    int p = t >> 2, q = t & 3;
    int b = p >> 13, thw = p & (ZTHW - 1);
    const float* zp = z + (size_t)b * CD * ZTHW + thw;
    float* op = out + OFF_ZQ + (size_t)b * CD * ZTHW + thw;
    int row = g_inds[p];
    const float4* er = (const float4*)(E + (size_t)row * CD + q * 64);

    float local = 0.f;
    #pragma unroll 4
    for (int c4 = 0; c4 < 16; c4++) {
        float4 e4 = er[c4];
        float ev[4] = {e4.x, e4.y, e4.z, e4.w};
        #pragma unroll
        for (int j = 0; j < 4; j++) {
            int c = q * 64 + c4 * 4 + j;
            float zv = zp[(size_t)c * ZTHW];
            float tt = __fsub_rn(ev[j], zv);
            op[(size_t)c * ZTHW] = __fadd_rn(zv, tt);
            local = fmaf(tt, tt, local);
        }
    }
    #pragma unroll
    for (int off = 16; off; off >>= 1) local += __shfl_xor_sync(0xFFFFFFFFu, local, off);
    __shared__ float ws[8];
    int lane = threadIdx.x & 31, w = threadIdx.x >> 5;
    if (lane == 0) ws[w] = local;
    __syncthreads();
    if (threadIdx.x == 0) {
        double s = 0.0;
        #pragma unroll
        for (int i = 0; i < 8; i++) s += (double)ws[i];
        g_part[blockIdx.x] = s;
    }
}

__global__ void vq_finalize(float* __restrict__ out, int npart) {
    if (threadIdx.x == 0 && blockIdx.x == 0) {
        double s = 0.0;
        for (int i = 0; i < npart; i++) s += g_part[i];
        out[OFF_LOSS] = (float)(1.25 * s / 8388608.0);
    }
}

// ---------------------------------------------------------------------------
extern "C" void kernel_launch(void* const* d_in, const int* in_sizes, int n_in,
                              void* d_out, int out_size) {
    const float* z = (const float*)d_in[0];
    const float* E = (const float*)d_in[1];
    float* out = (float*)d_out;

    conv_z<<<2048, 256>>>(z);
    conv_E<<<(NK * CD) / 1024, 256>>>(E);   // also zeroes g_nflag
    vq_enorm<<<128, 256>>>(E);
    vq_xnorm<<<1024, 256>>>(z);

    cudaFuncSetAttribute(vq_gemm_mma, cudaFuncAttributeMaxDynamicSharedMemorySize, SM_TOT);
    vq_gemm_mma<<<NPT / 128, 256, SM_TOT>>>(out);

    vq_refine<<<592, 256>>>(z, E, out);
    vq_out<<<512, 256>>>(z, E, out);
    vq_finalize<<<1, 32>>>(out, 512);
}

// round 10
// speedup vs baseline: 2.7197x; 1.9050x over previous
#include <cuda_runtime.h>
#include <cuda_fp16.h>
#include <float.h>
#include <stdint.h>

// Problem constants
#define CD   256
#define ZTHW 8192
#define NPT  32768
#define NK   1024

// Output layout (float32). OFF_D is ODD -> only scalar stores in d region.
#define OFF_ZQ   0
#define OFF_LOSS 8388608
#define OFF_INDS 8388609
#define OFF_D    8421377

#define GAP_THRESH  1e-4f    // flag threshold on fp16-path top-2 gap
#define CAND_MARGIN 4e-4f    // refine candidate margin (>=8 sigma of d-noise)

// Scratch globals
__device__ __align__(16) __half g_zth[NPT * CD];   // z^T fp16 [n][c]
__device__ __align__(16) __half g_Eh[NK * CD];     // E fp16 [k][c]
__device__ float  g_xn4[4][NPT];                   // per-64ch xnorm partials
__device__ float  g_xnorm[NPT];
__device__ float  g_enorm[NK];
__device__ int    g_inds[NPT];
__device__ double g_part[512];
__device__ int    g_nflag;
__device__ int    g_flag[NPT];

// ---------------------------------------------------------------------------
// PTX helpers (portable sm_80+: mma.sync / ldmatrix / cp.async)
// ---------------------------------------------------------------------------
__device__ __forceinline__ uint32_t smem_u32(const void* p) {
    uint32_t a;
    asm("{ .reg .u64 t; cvta.to.shared.u64 t, %1; cvt.u32.u64 %0, t; }" : "=r"(a) : "l"(p));
    return a;
}
__device__ __forceinline__ void ldsm_x4(uint32_t& r0, uint32_t& r1, uint32_t& r2,
                                        uint32_t& r3, uint32_t addr) {
    asm volatile("ldmatrix.sync.aligned.m8n8.x4.shared.b16 {%0,%1,%2,%3}, [%4];"
                 : "=r"(r0), "=r"(r1), "=r"(r2), "=r"(r3) : "r"(addr));
}
__device__ __forceinline__ void mma16816(float* c, const uint32_t* a, const uint32_t* b) {
    asm volatile(
        "mma.sync.aligned.m16n8k16.row.col.f32.f16.f16.f32 "
        "{%0,%1,%2,%3}, {%4,%5,%6,%7}, {%8,%9}, {%0,%1,%2,%3};"
        : "+f"(c[0]), "+f"(c[1]), "+f"(c[2]), "+f"(c[3])
        : "r"(a[0]), "r"(a[1]), "r"(a[2]), "r"(a[3]), "r"(b[0]), "r"(b[1]));
}
__device__ __forceinline__ void cp16(uint32_t dst, const void* src) {
    asm volatile("cp.async.cg.shared.global [%0], [%1], 16;" :: "r"(dst), "l"(src));
}
#define CP_COMMIT() asm volatile("cp.async.commit_group;" ::: "memory")
#define CP_WAIT(N)  asm volatile("cp.async.wait_group %0;" :: "n"(N) : "memory")

// GEMM smem layout (bytes) -- 2 CTAs/SM (2 x ~106.5KB < 228KB)
#define APAD   264                    // 256 halves + 8 pad (row stride 528B)
#define EPAD   72                     // 64 halves + 8 pad  (row stride 144B)
#define A_PLANE (128 * APAD * 2)      // 67584
#define SM_A    0
#define SM_E    A_PLANE               // 67584; 2 bufs x 128 x 144 = 36864
#define E_BUF   (128 * EPAD * 2)      // 18432
#define SM_XN   (SM_E + 2 * E_BUF)    // 104448 (128 floats)
#define SM_EN   (SM_XN + 512)         // 104960 (1024 floats enorm cache)
#define SM_TOT  (SM_EN + 4096)        // 109056

// ---------------------------------------------------------------------------
// Transpose z -> fp16 [N][C]  +  per-block xnorm partials (fused).
// Block covers 64 channels x 64 points.
// ---------------------------------------------------------------------------
__global__ __launch_bounds__(256) void conv_z(const float* __restrict__ z) {
    __shared__ float tile[64][65];
    const int bx = blockIdx.x;
    const int ct = bx & 3, tt = (bx >> 2) & 127, b = bx >> 9;
    const int tid = threadIdx.x;

    const int c_l = tid >> 4, t4 = (tid & 15) << 2;
    #pragma unroll
    for (int cc = 0; cc < 4; cc++) {
        const int c_idx = cc * 16 + c_l;
        const float4 v = *(const float4*)&z[((size_t)(b * CD + ct * 64 + c_idx)) * ZTHW
                                            + tt * 64 + t4];
        tile[c_idx][t4 + 0] = v.x; tile[c_idx][t4 + 1] = v.y;
        tile[c_idx][t4 + 2] = v.z; tile[c_idx][t4 + 3] = v.w;
    }
    __syncthreads();

    const int t_l = tid >> 2, cs = (tid & 3) << 4;
    const size_t n = (size_t)b * ZTHW + tt * 64 + t_l;
    __half h[16];
    float sq = 0.f;
    #pragma unroll
    for (int j = 0; j < 16; j++) {
        const float x = tile[cs + j][t_l];
        h[j] = __float2half_rn(x);
        sq = fmaf(x, x, sq);
    }
    __half* dh = g_zth + n * CD + ct * 64 + cs;
    *(uint4*)(dh + 0) = ((uint4*)h)[0];  *(uint4*)(dh + 8) = ((uint4*)h)[1];

    // reduce 4 lanes (tid&3) holding same point -> 64-ch partial
    sq += __shfl_xor_sync(0xFFFFFFFFu, sq, 1);
    sq += __shfl_xor_sync(0xFFFFFFFFu, sq, 2);
    if ((tid & 3) == 0) g_xn4[ct][n] = sq;
}

__global__ void xnorm_finish(void) {
    const int p = blockIdx.x * blockDim.x + threadIdx.x;
    g_xnorm[p] = (g_xn4[0][p] + g_xn4[1][p]) + (g_xn4[2][p] + g_xn4[3][p]);
}

// ---------------------------------------------------------------------------
// E -> fp16 + enorm (fused; warp per code row). Also zeroes g_nflag.
// ---------------------------------------------------------------------------
__global__ void conv_E(const float* __restrict__ E) {
    const int gt = blockIdx.x * blockDim.x + threadIdx.x;
    if (gt == 0) g_nflag = 0;
    const int row = gt >> 5, lane = gt & 31;
    if (row >= NK) return;
    const float* er = E + (size_t)row * CD;
    float s = 0.f;
    #pragma unroll
    for (int i = 0; i < 2; i++) {
        const int c = i * 128 + lane * 4;
        const float4 v = *(const float4*)&er[c];
        __half h[4] = {__float2half_rn(v.x), __float2half_rn(v.y),
                       __float2half_rn(v.z), __float2half_rn(v.w)};
        *(uint2*)&g_Eh[(size_t)row * CD + c] = *(uint2*)h;
        s = fmaf(v.x, v.x, s); s = fmaf(v.y, v.y, s);
        s = fmaf(v.z, v.z, s); s = fmaf(v.w, v.w, s);
    }
    #pragma unroll
    for (int off = 16; off; off >>= 1) s += __shfl_xor_sync(0xFFFFFFFFu, s, off);
    if (lane == 0) g_enorm[row] = s;
}

// ---------------------------------------------------------------------------
// mma.sync GEMM: CTA = 128 pts x 128 codes/ct-tile, 8 ct tiles, K=256.
// fp16 z plane resident; E streamed (cp.async dbl-buffer); 2 CTAs/SM.
// Top-2 tracked per point; small gaps flagged for exact refine.
// ---------------------------------------------------------------------------
extern __shared__ char dsm[];

__global__ void __launch_bounds__(256, 2) vq_gemm_mma(float* __restrict__ out) {
    const uint32_t smu = smem_u32(dsm);
    const int tid = threadIdx.x;
    const int lane = tid & 31, wid = tid >> 5;
    const int wy = wid >> 1, wx = wid & 1;
    const int n0 = blockIdx.x * 128;

    float* xn_sm = (float*)(dsm + SM_XN);
    float* en_sm = (float*)(dsm + SM_EN);
    if (tid < 128) xn_sm[tid] = g_xnorm[n0 + tid];
    #pragma unroll
    for (int i = 0; i < 4; i++) en_sm[i * 256 + tid] = g_enorm[i * 256 + tid];

    // Resident A (128 rows x 512B) + E stage 0; one cp.async group.
    {
        #pragma unroll
        for (int it = 0; it < 16; it++) {
            const int id = it * 256 + tid;           // 0..4095 16B chunks
            const int row = id >> 5;
            const int ch  = id & 31;
            cp16(smu + SM_A + row * (APAD * 2) + ch * 16,
                 g_zth + (size_t)(n0 + row) * CD + ch * 8);
        }
        #pragma unroll
        for (int it = 0; it < 4; it++) {
            const int id = it * 256 + tid;           // 0..1023
            const int code = id >> 3, ch = id & 7;   // stage0: ct=0, kq=0
            cp16(smu + SM_E + code * (EPAD * 2) + ch * 16,
                 g_Eh + (size_t)code * CD + ch * 8);
        }
        CP_COMMIT();
    }

    const uint32_t aBase = smu + SM_A + (wy * 32 + (lane & 15)) * (APAD * 2)
                           + ((lane & 16) ? 16 : 0);
    const uint32_t bBase = smu + SM_E
                           + (wx * 64 + (lane & 7) + ((lane & 16) ? 8 : 0)) * (EPAD * 2)
                           + ((lane & 8) ? 16 : 0);

    float acc[2][8][4];
    float best[4], sec[4];
    int   bidr[4];
    #pragma unroll
    for (int i = 0; i < 4; i++) { best[i] = FLT_MAX; sec[i] = FLT_MAX; bidr[i] = 0; }

    for (int s = 0; s < 32; s++) {                   // stage = ct*4 + kq
        const int ct = s >> 2, kq = s & 3, buf = s & 1;
        if ((s & 3) == 0) {
            #pragma unroll
            for (int mt = 0; mt < 2; mt++)
                #pragma unroll
                for (int nt = 0; nt < 8; nt++)
                    #pragma unroll
                    for (int c = 0; c < 4; c++) acc[mt][nt][c] = 0.f;
        }
        if (s < 31) {
            const int ns = s + 1;
            const int nct = ns >> 2, nkq = ns & 3, nbuf = ns & 1;
            #pragma unroll
            for (int it = 0; it < 4; it++) {
                const int id = it * 256 + tid;
                const int code = id >> 3, ch = id & 7;
                cp16(smu + SM_E + nbuf * E_BUF + code * (EPAD * 2) + ch * 16,
                     g_Eh + (size_t)(nct * 128 + code) * CD + nkq * 64 + ch * 8);
            }
            CP_COMMIT();
            CP_WAIT(1);
        } else {
            CP_WAIT(0);
        }
        __syncthreads();

        #pragma unroll
        for (int step = 0; step < 4; step++) {
            const int kh_abs = kq * 64 + step * 16;
            const int kh_loc = step * 16;
            uint32_t bf[8][2];
            #pragma unroll
            for (int p4 = 0; p4 < 4; p4++) {
                uint32_t r0, r1, r2, r3;
                ldsm_x4(r0, r1, r2, r3,
                        bBase + buf * E_BUF + p4 * 16 * (EPAD * 2) + kh_loc * 2);
                bf[p4 * 2][0] = r0; bf[p4 * 2][1] = r1;
                bf[p4 * 2 + 1][0] = r2; bf[p4 * 2 + 1][1] = r3;
            }
            uint32_t af[2][4];
            #pragma unroll
            for (int mt = 0; mt < 2; mt++)
                ldsm_x4(af[mt][0], af[mt][1], af[mt][2], af[mt][3],
                        aBase + mt * 16 * (APAD * 2) + kh_abs * 2);
            #pragma unroll
            for (int mt = 0; mt < 2; mt++)
                #pragma unroll
                for (int nt = 0; nt < 8; nt++)
                    mma16816(acc[mt][nt], af[mt], bf[nt]);
        }

        if ((s & 3) == 3) {
            const int k0 = ct * 128;
            #pragma unroll
            for (int mt = 0; mt < 2; mt++) {
                #pragma unroll
                for (int rsel = 0; rsel < 2; rsel++) {
                    const int bi_ = mt * 2 + rsel;
                    const int row = wy * 32 + mt * 16 + rsel * 8 + (lane >> 2);
                    const float xnv = xn_sm[row];
                    float* dr = out + OFF_D + (size_t)(n0 + row) * NK + k0;
                    #pragma unroll
                    for (int nt = 0; nt < 8; nt++) {
                        const int col0 = wx * 64 + nt * 8 + 2 * (lane & 3);
                        const float d0 = xnv + en_sm[k0 + col0]
                                       - 2.0f * acc[mt][nt][rsel * 2];
                        const float d1 = xnv + en_sm[k0 + col0 + 1]
                                       - 2.0f * acc[mt][nt][rsel * 2 + 1];
                        dr[col0] = d0;
                        dr[col0 + 1] = d1;
                        if (d0 < best[bi_]) { sec[bi_] = best[bi_]; best[bi_] = d0; bidr[bi_] = k0 + col0; }
                        else if (d0 < sec[bi_]) sec[bi_] = d0;
                        if (d1 < best[bi_]) { sec[bi_] = best[bi_]; best[bi_] = d1; bidr[bi_] = k0 + col0 + 1; }
                        else if (d1 < sec[bi_]) sec[bi_] = d1;
                    }
                }
            }
        }
        __syncthreads();
    }

    // quad reduce (lanes differing in bits 0-1 share rows): top-2 merge
    #pragma unroll
    for (int i = 0; i < 4; i++) {
        #pragma unroll
        for (int off = 1; off <= 2; off <<= 1) {
            const float v1o = __shfl_xor_sync(0xFFFFFFFFu, best[i], off);
            const int   i1o = __shfl_xor_sync(0xFFFFFFFFu, bidr[i], off);
            const float v2o = __shfl_xor_sync(0xFFFFFFFFu, sec[i], off);
            if (v1o < best[i] || (v1o == best[i] && i1o < bidr[i])) {
                sec[i]  = fminf(best[i], v2o);
                best[i] = v1o; bidr[i] = i1o;
            } else {
                sec[i] = fminf(sec[i], v1o);
            }
        }
    }
    // cross warp-pair reduce via smem scratch (E buffers dead after last sync)
    float* sv1 = (float*)(dsm + SM_E);
    int*   si1 = (int*)(dsm + SM_E + 512);
    float* sv2 = (float*)(dsm + SM_E + 1024);
    if (wx == 1 && (lane & 3) == 0) {
        #pragma unroll
        for (int i = 0; i < 4; i++) {
            const int row = wy * 32 + i * 8 + (lane >> 2);
            sv1[row] = best[i]; si1[row] = bidr[i]; sv2[row] = sec[i];
        }
    }
    __syncthreads();
    if (wx == 0 && (lane & 3) == 0) {
        #pragma unroll
        for (int i = 0; i < 4; i++) {
            const int row = wy * 32 + i * 8 + (lane >> 2);
            float v1 = best[i], v2 = sec[i]; int i1 = bidr[i];
            const float o1 = sv1[row], o2 = sv2[row]; const int oi = si1[row];
            if (o1 < v1 || (o1 == v1 && oi < i1)) {
                v2 = fminf(v1, o2); v1 = o1; i1 = oi;
            } else {
                v2 = fminf(v2, o1);
            }
            const int n = n0 + row;
            g_inds[n] = i1;
            out[OFF_INDS + n] = (float)i1;
            if (v2 - v1 < GAP_THRESH) {
                int slot = atomicAdd(&g_nflag, 1);
                g_flag[slot] = n;
            }
        }
    }
}

// ---------------------------------------------------------------------------
// Refine v2: for each flagged point, scan its (already-written) d row, take
// candidates within CAND_MARGIN of the row min, recompute those EXACTLY in
// fp32 (same warp-dot as before), pick lexicographic (d, k) min. The exact
// argmin's fp16-d is within ~5 sigma of the row min, so it is always in the
// candidate set. Traffic: ~10KB/point instead of 1MB/point.
// ---------------------------------------------------------------------------
__global__ __launch_bounds__(256) void vq_refine(const float* __restrict__ z,
                                                 const float* __restrict__ E,
                                                 float* __restrict__ out) {
    __shared__ float zs[256];
    __shared__ float rv[8];
    __shared__ int   ri[8];
    __shared__ int   cand[64];
    __shared__ int   ncand;
    const int nf = g_nflag;
    const int tid = threadIdx.x, w = tid >> 5, lane = tid & 31;

    for (int f = blockIdx.x; f < nf; f += gridDim.x) {
        const int p = g_flag[f];
        const int b = p >> 13, thw = p & (ZTHW - 1);
        const float* zp = z + (size_t)b * CD * ZTHW + thw;
        zs[tid] = zp[(size_t)tid * ZTHW];
        if (tid == 0) ncand = 0;
        __syncthreads();

        const float* drow = out + OFF_D + (size_t)p * NK;
        // pass 1: row min (value only; margin makes index irrelevant here)
        float bv = FLT_MAX;
        float dv[4];
        #pragma unroll
        for (int j = 0; j < 4; j++) {
            dv[j] = drow[j * 256 + tid];
            bv = fminf(bv, dv[j]);
        }
        #pragma unroll
        for (int off = 16; off; off >>= 1)
            bv = fminf(bv, __shfl_xor_sync(0xFFFFFFFFu, bv, off));
        if (lane == 0) rv[w] = bv;
        __syncthreads();
        if (tid == 0) {
            float v = rv[0];
            #pragma unroll
            for (int w2 = 1; w2 < 8; w2++) v = fminf(v, rv[w2]);
            rv[0] = v;
        }
        __syncthreads();
        const float vmin = rv[0];

        // pass 2: gather candidates (order nondeterministic; selection below
        // is order-independent lexicographic min, so result is deterministic)
        #pragma unroll
        for (int j = 0; j < 4; j++) {
            if (dv[j] < vmin + CAND_MARGIN) {
                const int s = atomicAdd(&ncand, 1);
                if (s < 64) cand[s] = j * 256 + tid;
            }
        }
        __syncthreads();
        const int nc = min(ncand, 64);

        // pass 3: exact fp32 d for candidates; warp ci-strided
        float cbv = FLT_MAX; int cbi = 0x7FFFFFFF;
        const float xn = g_xnorm[p];
        for (int ci = w; ci < nc; ci += 8) {
            const int k = cand[ci];
            const float* er = E + (size_t)k * CD;
            float dot = 0.f;
            #pragma unroll
            for (int i = 0; i < 8; i++)
                dot = fmaf(er[lane + 32 * i], zs[lane + 32 * i], dot);
            #pragma unroll
            for (int off = 16; off; off >>= 1)
                dot += __shfl_xor_sync(0xFFFFFFFFu, dot, off);
            const float d = xn + g_enorm[k] - 2.0f * dot;
            if (d < cbv || (d == cbv && k < cbi)) { cbv = d; cbi = k; }
        }
        if (lane == 0) { rv[w] = cbv; ri[w] = cbi; }
        __syncthreads();
        if (tid == 0) {
            float v = rv[0]; int id = ri[0];
            #pragma unroll
            for (int w2 = 1; w2 < 8; w2++)
                if (rv[w2] < v || (rv[w2] == v && ri[w2] < id)) { v = rv[w2]; id = ri[w2]; }
            g_inds[p] = id;
            out[OFF_INDS + p] = (float)id;
        }
        __syncthreads();
    }
}

// ---------------------------------------------------------------------------
// Gather z_q, z_q_ste = z + (z_q - z), deterministic loss partials.
// ---------------------------------------------------------------------------
__global__ __launch_bounds__(256) void vq_out(const float* __restrict__ z,
                                              const float* __restrict__ E,
                                              float* __restrict__ out) {
    int t = blockIdx.x * blockDim.x + threadIdx.x;
    int p = t >> 2, q = t & 3;
    int b = p >> 13, thw = p & (ZTHW - 1);
    const float* zp = z + (size_t)b * CD * ZTHW + thw;
    float* op = out + OFF_ZQ + (size_t)b * CD * ZTHW + thw;
    int row = g_inds[p];
    const float4* er = (const float4*)(E + (size_t)row * CD + q * 64);

    float local = 0.f;
    #pragma unroll 4
    for (int c4 = 0; c4 < 16; c4++) {
        float4 e4 = er[c4];
        float ev[4] = {e4.x, e4.y, e4.z, e4.w};
        #pragma unroll
        for (int j = 0; j < 4; j++) {
            int c = q * 64 + c4 * 4 + j;
            float zv = zp[(size_t)c * ZTHW];
            float tt = __fsub_rn(ev[j], zv);
            op[(size_t)c * ZTHW] = __fadd_rn(zv, tt);
            local = fmaf(tt, tt, local);
        }
    }
    #pragma unroll
    for (int off = 16; off; off >>= 1) local += __shfl_xor_sync(0xFFFFFFFFu, local, off);
    __shared__ float ws[8];
    int lane = threadIdx.x & 31, w = threadIdx.x >> 5;
    if (lane == 0) ws[w] = local;
    __syncthreads();
    if (threadIdx.x == 0) {
        double s = 0.0;
        #pragma unroll
        for (int i = 0; i < 8; i++) s += (double)ws[i];
        g_part[blockIdx.x] = s;
    }
}

__global__ void vq_finalize(float* __restrict__ out, int npart) {
    if (threadIdx.x == 0 && blockIdx.x == 0) {
        double s = 0.0;
        for (int i = 0; i < npart; i++) s += g_part[i];
        out[OFF_LOSS] = (float)(1.25 * s / 8388608.0);
    }
}

// ---------------------------------------------------------------------------
extern "C" void kernel_launch(void* const* d_in, const int* in_sizes, int n_in,
                              void* d_out, int out_size) {
    const float* z = (const float*)d_in[0];
    const float* E = (const float*)d_in[1];
    float* out = (float*)d_out;

    conv_z<<<2048, 256>>>(z);             // also emits xnorm partials
    conv_E<<<128, 256>>>(E);              // also emits enorm, zeroes g_nflag
    xnorm_finish<<<128, 256>>>();

    cudaFuncSetAttribute(vq_gemm_mma, cudaFuncAttributeMaxDynamicSharedMemorySize, SM_TOT);
    vq_gemm_mma<<<NPT / 128, 256, SM_TOT>>>(out);

    vq_refine<<<592, 256>>>(z, E, out);
    vq_out<<<512, 256>>>(z, E, out);
    vq_finalize<<<1, 32>>>(out, 512);
}